// round 15
// baseline (speedup 1.0000x reference)
#include <cuda_runtime.h>
#include <math_constants.h>

#define S_TOTAL 4096
#define BATCH   64
#define DIM     256
#define CHUNKS  32
#define CHUNK_S 128   // S_TOTAL / CHUNKS

// Scratch (allocation-free rule: __device__ globals; zero-initialized at load,
// masked chunks' g_acc/g_m/g_l slots are never written -> stay finite 0).
__device__ float g_key[BATCH * DIM];
__device__ float g_m[BATCH * CHUNKS];
__device__ float g_l[BATCH * CHUNKS];
__device__ float g_acc[BATCH * CHUNKS * DIM];
__device__ int   g_len_is64;   // 1 if sequence_lengths is int64, 0 if int32

__device__ __forceinline__ int load_len(const void* lens, int b) {
    if (g_len_is64)
        return (int)((const long long*)lens)[b];
    return ((const int*)lens)[b];
}

// ---------------------------------------------------------------------------
// Kernel 1: key[b][d] = bias[d] + sum_j query[b][j] * W[d][j]
// grid (BATCH, 2), 256 threads: block (b, y) computes d in [y*128, y*128+128),
// warp w owns d = y*128 + w + 8*i, i in [0,16). Lanes stride over j with two
// coalesced float4 loads per W row; q fragment register-resident; shuffle
// reduce per output. 16 independent output chains per warp for ILP/MLP;
// 128 blocks = single wave.
// Block (0,0)/thread 0 also detects the sequence_lengths dtype: lengths are
// all >= 1, so viewing the buffer as int32 words, odd words are ALL zero iff
// the layout is int64 (high halves). flash_kernel launches after this kernel
// completes, so the flag write is ordered.
// ---------------------------------------------------------------------------
__global__ __launch_bounds__(DIM)
void key_kernel(const float* __restrict__ q,
                const float* __restrict__ W,
                const float* __restrict__ bias,
                const int*   __restrict__ lens_w) {
    const int b = blockIdx.x;
    const int y = blockIdx.y;
    const int t = threadIdx.x;
    if (b == 0 && y == 0 && t == 0) {
        int any_odd_nonzero = 0;
#pragma unroll
        for (int i = 1; i < 64; i += 2)
            any_odd_nonzero |= (lens_w[i] != 0);
        g_len_is64 = any_odd_nonzero ? 0 : 1;
    }
    __shared__ float qs[DIM];
    qs[t] = q[b * DIM + t];
    __syncthreads();

    const int lane = t & 31;
    const int wrp  = t >> 5;
    const float4* q4 = reinterpret_cast<const float4*>(qs);
    const float4 a0 = q4[lane];        // j = lane*4 .. lane*4+3
    const float4 a1 = q4[lane + 32];   // j = 128 + lane*4 ..

#pragma unroll 4
    for (int i = 0; i < 16; i++) {
        const int d = y * 128 + wrp + i * 8;
        const float4* W4 = reinterpret_cast<const float4*>(W + (size_t)d * DIM);
        const float4 w0 = W4[lane];
        const float4 w1 = W4[lane + 32];
        float p = w0.x * a0.x + w0.y * a0.y + w0.z * a0.z + w0.w * a0.w
                + w1.x * a1.x + w1.y * a1.y + w1.z * a1.z + w1.w * a1.w;
#pragma unroll
        for (int off = 16; off; off >>= 1)
            p += __shfl_xor_sync(0xffffffffu, p, off);
        if (lane == 0)
            g_key[b * DIM + d] = bias[d] + p;
    }
}

// ---------------------------------------------------------------------------
// Kernel 2: flash-style partial softmax-attention, warp-autonomous version.
// Block (chunk c, batch b), 8 warps. Warp w owns rows w, w+8, ... of the
// chunk (disjoint), streaming each row fragment (lane: 8 floats = 2 LDG.128,
// coalesced across the warp) straight into registers with a 4-row-deep
// register pipeline. Per-warp online softmax (m, l, acc[8]) — no SMEM
// staging, no __syncthreads in the mainloop. One merge of the 8 warp
// partials at the end (2 syncs/block).
// ---------------------------------------------------------------------------
__global__ __launch_bounds__(DIM)
void flash_kernel(const float* __restrict__ attended,
                  const void* __restrict__ lens) {
    const int c   = blockIdx.x;
    const int b   = blockIdx.y;
    const int tid = threadIdx.x;
    const int len = load_len(lens, b);
    const int sbeg = c * CHUNK_S;
    const int idx  = b * CHUNKS + c;

    if (len <= sbeg) {
        if (tid == 0) g_l[idx] = 0.f;   // mark invalid; reducer gives it weight 0
        return;
    }

    const int send  = min(sbeg + CHUNK_S, len);
    const int nrows = send - sbeg;           // >= 1
    const int lane  = tid & 31;
    const int w     = tid >> 5;
    // warp w's rows: r = w + 8*j, r < nrows  ->  j < nj
    const int nj = (nrows - w + 7) >> 3;     // nrows>=1, w<=7 -> argument >= 1

    __shared__ float sm_m[8], sm_l[8], sm_w8[8];
    __shared__ float sm_acc[8 * DIM];        // 8 KB

    // key fragment for this lane (dims lane*8 .. lane*8+7)
    const float4* kp = reinterpret_cast<const float4*>(g_key + b * DIM) + lane * 2;
    const float4 k0 = kp[0];
    const float4 k1 = kp[1];

    // attended[s][b][lane*8 ..] for s = sbeg + r
    const float4* abase = reinterpret_cast<const float4*>(attended)
        + ((size_t)sbeg * BATCH + b) * (DIM / 4) + lane * 2;
    const size_t rstride = (size_t)BATCH * (DIM / 4);   // one s step, in float4s

    float m = -CUDART_INF_F, l = 0.f;
    float acc0 = 0.f, acc1 = 0.f, acc2 = 0.f, acc3 = 0.f;
    float acc4 = 0.f, acc5 = 0.f, acc6 = 0.f, acc7 = 0.f;

    float4 fa0, fb0, fa1, fb1, fa2, fb2, fa3, fb3;

#define LOADROW(A, B, J) do {                                            \
        const int _j = (J);                                              \
        if (_j < nj) {                                                   \
            const float4* _p = abase + (size_t)(w + 8 * _j) * rstride;   \
            A = _p[0]; B = _p[1];                                        \
        }                                                                \
    } while (0)

#define PROCESS(A, B) do {                                               \
        const float4 ra = A, rb = B;                                     \
        float s_ = ra.x * k0.x + ra.y * k0.y + ra.z * k0.z + ra.w * k0.w \
                 + rb.x * k1.x + rb.y * k1.y + rb.z * k1.z + rb.w * k1.w;\
        s_ += __shfl_xor_sync(0xffffffffu, s_, 16);                      \
        s_ += __shfl_xor_sync(0xffffffffu, s_, 8);                       \
        s_ += __shfl_xor_sync(0xffffffffu, s_, 4);                       \
        s_ += __shfl_xor_sync(0xffffffffu, s_, 2);                       \
        s_ += __shfl_xor_sync(0xffffffffu, s_, 1);                       \
        const float m_new = fmaxf(m, s_);                                \
        const float scale = __expf(m - m_new);                           \
        const float p     = __expf(s_ - m_new);                          \
        l = l * scale + p;                                               \
        m = m_new;                                                       \
        acc0 = acc0 * scale + p * ra.x; acc1 = acc1 * scale + p * ra.y;  \
        acc2 = acc2 * scale + p * ra.z; acc3 = acc3 * scale + p * ra.w;  \
        acc4 = acc4 * scale + p * rb.x; acc5 = acc5 * scale + p * rb.y;  \
        acc6 = acc6 * scale + p * rb.z; acc7 = acc7 * scale + p * rb.w;  \
    } while (0)

    LOADROW(fa0, fb0, 0);
    LOADROW(fa1, fb1, 1);
    LOADROW(fa2, fb2, 2);
    LOADROW(fa3, fb3, 3);

    for (int j0 = 0; j0 < nj; j0 += 4) {
        if (j0 + 0 < nj) { float4 A = fa0, B = fb0; LOADROW(fa0, fb0, j0 + 4); PROCESS(A, B); }
        if (j0 + 1 < nj) { float4 A = fa1, B = fb1; LOADROW(fa1, fb1, j0 + 5); PROCESS(A, B); }
        if (j0 + 2 < nj) { float4 A = fa2, B = fb2; LOADROW(fa2, fb2, j0 + 6); PROCESS(A, B); }
        if (j0 + 3 < nj) { float4 A = fa3, B = fb3; LOADROW(fa3, fb3, j0 + 7); PROCESS(A, B); }
    }
#undef LOADROW
#undef PROCESS

    // --- merge 8 warp partials ---
    if (lane == 0) { sm_m[w] = m; sm_l[w] = l; }
    float4* dst = reinterpret_cast<float4*>(sm_acc + w * DIM) + lane * 2;
    dst[0] = make_float4(acc0, acc1, acc2, acc3);
    dst[1] = make_float4(acc4, acc5, acc6, acc7);
    __syncthreads();

    if (tid < 8) {
        float M = -CUDART_INF_F;
#pragma unroll
        for (int i = 0; i < 8; i++)
            if (sm_l[i] > 0.f) M = fmaxf(M, sm_m[i]);
        sm_w8[tid] = (sm_l[tid] > 0.f) ? __expf(sm_m[tid] - M) : 0.f;
        if (tid == 0) {
            float L = 0.f;
#pragma unroll
            for (int i = 0; i < 8; i++)
                if (sm_l[i] > 0.f) L += sm_l[i] * __expf(sm_m[i] - M);
            g_m[idx] = M;
            g_l[idx] = L;
        }
    }
    __syncthreads();

    float a = 0.f;
#pragma unroll
    for (int i = 0; i < 8; i++)
        a += sm_w8[i] * sm_acc[i * DIM + tid];
    g_acc[(size_t)idx * DIM + tid] = a;
}

// ---------------------------------------------------------------------------
// Kernel 3: merge CHUNKS partials per batch row, normalize, write output.
// grid (BATCH, 4) x 64 threads: block handles dims [64*y, 64*y+64).
// Warp 0 computes merge weights; the dim loop is 32 unconditional, fully
// unrolled coalesced loads (max MLP). Masked chunks: weight=0, g_acc slot=0.
// ---------------------------------------------------------------------------
__global__ __launch_bounds__(64)
void reduce_kernel(float* __restrict__ out) {
    const int b   = blockIdx.x;
    const int d   = blockIdx.y * 64 + threadIdx.x;
    const int tid = threadIdx.x;

    __shared__ float wsh[CHUNKS];
    __shared__ float Lsh;

    if (tid < 32) {
        const float lc = g_l[b * CHUNKS + tid];
        const float mv = g_m[b * CHUNKS + tid];
        float M = (lc > 0.f) ? mv : -CUDART_INF_F;
#pragma unroll
        for (int off = 16; off; off >>= 1)
            M = fmaxf(M, __shfl_xor_sync(0xffffffffu, M, off));
        const float wgt = (lc > 0.f) ? __expf(mv - M) : 0.f;
        float L = lc * wgt;
#pragma unroll
        for (int off = 16; off; off >>= 1)
            L += __shfl_xor_sync(0xffffffffu, L, off);
        wsh[tid] = wgt;
        if (tid == 0) Lsh = L;
    }
    __syncthreads();

    const float* base = g_acc + (size_t)b * CHUNKS * DIM + d;
    float a = 0.f;
#pragma unroll
    for (int ci = 0; ci < CHUNKS; ci++)
        a += wsh[ci] * base[(size_t)ci * DIM];

    out[b * DIM + d] = a / Lsh;
}

// ---------------------------------------------------------------------------
// Launch. Inputs identified by element count (robust to metadata ordering):
//   query 16384 f32, attended 67108864 f32, sequence_lengths 64 (i32 or i64),
//   W 65536 f32, b 256 f32. Output: [B, D] f32.
// ---------------------------------------------------------------------------
extern "C" void kernel_launch(void* const* d_in, const int* in_sizes, int n_in,
                              void* d_out, int out_size) {
    const float* q = nullptr;
    const float* att = nullptr;
    const void*  lens = nullptr;
    const float* W = nullptr;
    const float* bias = nullptr;

    for (int i = 0; i < n_in; i++) {
        switch (in_sizes[i]) {
            case BATCH * DIM:                 q    = (const float*)d_in[i]; break;
            case S_TOTAL * BATCH * DIM:       att  = (const float*)d_in[i]; break;
            case BATCH:                       lens = d_in[i];               break;
            case DIM * DIM:                   W    = (const float*)d_in[i]; break;
            case DIM:                         bias = (const float*)d_in[i]; break;
            default: break;
        }
    }

    float* out = (float*)d_out;

    dim3 kgrid(BATCH, 2);
    key_kernel<<<kgrid, DIM>>>(q, W, bias, (const int*)lens);
    dim3 grid(CHUNKS, BATCH);
    flash_kernel<<<grid, DIM>>>(att, lens);
    dim3 rgrid(BATCH, 4);
    reduce_kernel<<<rgrid, 64>>>(out);
}

// round 16
// speedup vs baseline: 1.1611x; 1.1611x over previous
#include <cuda_runtime.h>
#include <math_constants.h>

#define S_TOTAL 4096
#define BATCH   64
#define DIM     256
#define CHUNKS  32
#define CHUNK_S 128   // S_TOTAL / CHUNKS

// Scratch (allocation-free rule: __device__ globals; zero-initialized at load,
// masked chunks' g_acc/g_m/g_l slots are never written -> stay finite 0).
__device__ float g_key[BATCH * DIM];
__device__ float g_m[BATCH * CHUNKS];
__device__ float g_l[BATCH * CHUNKS];
__device__ float g_acc[BATCH * CHUNKS * DIM];
__device__ int   g_len_is64;   // 1 if sequence_lengths is int64, 0 if int32

__device__ __forceinline__ int load_len(const void* lens, int b) {
    if (g_len_is64)
        return (int)((const long long*)lens)[b];
    return ((const int*)lens)[b];
}

// ---------------------------------------------------------------------------
// Kernel 1: key[b][d] = bias[d] + sum_j query[b][j] * W[d][j]
// Cold-DRAM-latency bound (W evicted from L2 by the attended stream each
// replay) -> maximize chip-wide MLP: grid (BATCH, 8) = 512 blocks, 256
// threads. Block (b, y) covers d in [y*32, y*32+32); warp w owns 4 outputs
// d = y*32 + w*4 + i. All 8 W loads (2 float4 per output) issue before any
// reduction; 4 independent shuffle chains interleave.
// Block (0,0)/thread 0 also detects the sequence_lengths dtype: lengths are
// all >= 1, so viewing the buffer as int32 words, odd words are ALL zero iff
// the layout is int64 (high halves). flash_kernel launches after this kernel
// completes, so the flag write is ordered.
// ---------------------------------------------------------------------------
__global__ __launch_bounds__(DIM)
void key_kernel(const float* __restrict__ q,
                const float* __restrict__ W,
                const float* __restrict__ bias,
                const int*   __restrict__ lens_w) {
    const int b = blockIdx.x;
    const int y = blockIdx.y;
    const int t = threadIdx.x;
    if (b == 0 && y == 0 && t == 0) {
        int any_odd_nonzero = 0;
#pragma unroll
        for (int i = 1; i < 64; i += 2)
            any_odd_nonzero |= (lens_w[i] != 0);
        g_len_is64 = any_odd_nonzero ? 0 : 1;
    }
    __shared__ float qs[DIM];
    qs[t] = q[b * DIM + t];
    __syncthreads();

    const int lane = t & 31;
    const int wrp  = t >> 5;
    const float4* q4 = reinterpret_cast<const float4*>(qs);
    const float4 a0 = q4[lane];        // j = lane*4 .. lane*4+3
    const float4 a1 = q4[lane + 32];   // j = 128 + lane*4 ..

    const int d0 = y * 32 + wrp * 4;
    float4 w0[4], w1[4];
#pragma unroll
    for (int i = 0; i < 4; i++) {      // issue all 8 loads first (MLP)
        const float4* W4 = reinterpret_cast<const float4*>(W + (size_t)(d0 + i) * DIM);
        w0[i] = W4[lane];
        w1[i] = W4[lane + 32];
    }
#pragma unroll
    for (int i = 0; i < 4; i++) {
        float p = w0[i].x * a0.x + w0[i].y * a0.y + w0[i].z * a0.z + w0[i].w * a0.w
                + w1[i].x * a1.x + w1[i].y * a1.y + w1[i].z * a1.z + w1[i].w * a1.w;
#pragma unroll
        for (int off = 16; off; off >>= 1)
            p += __shfl_xor_sync(0xffffffffu, p, off);
        if (lane == 0)
            g_key[b * DIM + d0 + i] = bias[d0 + i] + p;
    }
}

// ---------------------------------------------------------------------------
// Kernel 2: flash-style partial softmax-attention, warp-autonomous, with
// 2-row joint softmax updates to halve the serial m/l/acc dependency chain.
// Block (chunk c, batch b), 8 warps. Warp w owns rows w, w+8, ... of the
// chunk (disjoint); lane streams its 32B row fragment straight from GMEM
// (2 coalesced LDG.128), 4-row register pipeline. No SMEM staging, no syncs
// in the mainloop; one 8-way merge at the end.
// ---------------------------------------------------------------------------
__global__ __launch_bounds__(DIM)
void flash_kernel(const float* __restrict__ attended,
                  const void* __restrict__ lens) {
    const int c   = blockIdx.x;
    const int b   = blockIdx.y;
    const int tid = threadIdx.x;
    const int len = load_len(lens, b);
    const int sbeg = c * CHUNK_S;
    const int idx  = b * CHUNKS + c;

    if (len <= sbeg) {
        if (tid == 0) g_l[idx] = 0.f;   // mark invalid; reducer gives it weight 0
        return;
    }

    const int send  = min(sbeg + CHUNK_S, len);
    const int nrows = send - sbeg;           // >= 1
    const int lane  = tid & 31;
    const int w     = tid >> 5;
    // warp w's rows: r = w + 8*j, r < nrows  ->  j < nj
    const int nj = (nrows - w + 7) >> 3;     // nrows>=1, w<=7 -> argument >= 1

    __shared__ float sm_m[8], sm_l[8], sm_w8[8];
    __shared__ float sm_acc[8 * DIM];        // 8 KB

    // key fragment for this lane (dims lane*8 .. lane*8+7)
    const float4* kp = reinterpret_cast<const float4*>(g_key + b * DIM) + lane * 2;
    const float4 k0 = kp[0];
    const float4 k1 = kp[1];

    // attended[s][b][lane*8 ..] for s = sbeg + r
    const float4* abase = reinterpret_cast<const float4*>(attended)
        + ((size_t)sbeg * BATCH + b) * (DIM / 4) + lane * 2;
    const size_t rstride = (size_t)BATCH * (DIM / 4);   // one s step, in float4s

    float m = -CUDART_INF_F, l = 0.f;
    float acc0 = 0.f, acc1 = 0.f, acc2 = 0.f, acc3 = 0.f;
    float acc4 = 0.f, acc5 = 0.f, acc6 = 0.f, acc7 = 0.f;

    float4 fa0, fb0, fa1, fb1, fa2, fb2, fa3, fb3;

#define LOADROW(A, B, J) do {                                            \
        const int _j = (J);                                              \
        if (_j < nj) {                                                   \
            const float4* _p = abase + (size_t)(w + 8 * _j) * rstride;   \
            A = _p[0]; B = _p[1];                                        \
        }                                                                \
    } while (0)

#define DOT(S, A, B) do {                                                \
        S = A.x * k0.x + A.y * k0.y + A.z * k0.z + A.w * k0.w            \
          + B.x * k1.x + B.y * k1.y + B.z * k1.z + B.w * k1.w;           \
        S += __shfl_xor_sync(0xffffffffu, S, 16);                        \
        S += __shfl_xor_sync(0xffffffffu, S, 8);                         \
        S += __shfl_xor_sync(0xffffffffu, S, 4);                         \
        S += __shfl_xor_sync(0xffffffffu, S, 2);                         \
        S += __shfl_xor_sync(0xffffffffu, S, 1);                         \
    } while (0)

    // Joint update for two rows: one m/l/acc carry step per pair.
#define PROCESS2(A0, B0, A1, B1) do {                                    \
        float s0, s1;                                                    \
        DOT(s0, A0, B0);                                                 \
        DOT(s1, A1, B1);                                                 \
        const float m_new = fmaxf(m, fmaxf(s0, s1));                     \
        const float scale = __expf(m - m_new);                           \
        const float p0    = __expf(s0 - m_new);                          \
        const float p1    = __expf(s1 - m_new);                          \
        l = l * scale + p0 + p1;                                         \
        m = m_new;                                                       \
        acc0 = acc0 * scale + p0 * A0.x + p1 * A1.x;                     \
        acc1 = acc1 * scale + p0 * A0.y + p1 * A1.y;                     \
        acc2 = acc2 * scale + p0 * A0.z + p1 * A1.z;                     \
        acc3 = acc3 * scale + p0 * A0.w + p1 * A1.w;                     \
        acc4 = acc4 * scale + p0 * B0.x + p1 * B1.x;                     \
        acc5 = acc5 * scale + p0 * B0.y + p1 * B1.y;                     \
        acc6 = acc6 * scale + p0 * B0.z + p1 * B1.z;                     \
        acc7 = acc7 * scale + p0 * B0.w + p1 * B1.w;                     \
    } while (0)

#define PROCESS1(A, B) do {                                              \
        float s_;                                                        \
        DOT(s_, A, B);                                                   \
        const float m_new = fmaxf(m, s_);                                \
        const float scale = __expf(m - m_new);                           \
        const float p     = __expf(s_ - m_new);                          \
        l = l * scale + p;                                               \
        m = m_new;                                                       \
        acc0 = acc0 * scale + p * A.x; acc1 = acc1 * scale + p * A.y;    \
        acc2 = acc2 * scale + p * A.z; acc3 = acc3 * scale + p * A.w;    \
        acc4 = acc4 * scale + p * B.x; acc5 = acc5 * scale + p * B.y;    \
        acc6 = acc6 * scale + p * B.z; acc7 = acc7 * scale + p * B.w;    \
    } while (0)

    LOADROW(fa0, fb0, 0);
    LOADROW(fa1, fb1, 1);
    LOADROW(fa2, fb2, 2);
    LOADROW(fa3, fb3, 3);

    for (int j0 = 0; j0 < nj; j0 += 4) {
        if (j0 + 1 < nj) {
            float4 A0 = fa0, B0 = fb0, A1 = fa1, B1 = fb1;
            LOADROW(fa0, fb0, j0 + 4);
            LOADROW(fa1, fb1, j0 + 5);
            PROCESS2(A0, B0, A1, B1);
        } else if (j0 < nj) {
            float4 A0 = fa0, B0 = fb0;
            PROCESS1(A0, B0);
        }
        if (j0 + 3 < nj) {
            float4 A0 = fa2, B0 = fb2, A1 = fa3, B1 = fb3;
            LOADROW(fa2, fb2, j0 + 6);
            LOADROW(fa3, fb3, j0 + 7);
            PROCESS2(A0, B0, A1, B1);
        } else if (j0 + 2 < nj) {
            float4 A0 = fa2, B0 = fb2;
            PROCESS1(A0, B0);
        }
    }
#undef LOADROW
#undef DOT
#undef PROCESS2
#undef PROCESS1

    // --- merge 8 warp partials ---
    if (lane == 0) { sm_m[w] = m; sm_l[w] = l; }
    float4* dst = reinterpret_cast<float4*>(sm_acc + w * DIM) + lane * 2;
    dst[0] = make_float4(acc0, acc1, acc2, acc3);
    dst[1] = make_float4(acc4, acc5, acc6, acc7);
    __syncthreads();

    if (tid < 8) {
        float M = -CUDART_INF_F;
#pragma unroll
        for (int i = 0; i < 8; i++)
            if (sm_l[i] > 0.f) M = fmaxf(M, sm_m[i]);
        sm_w8[tid] = (sm_l[tid] > 0.f) ? __expf(sm_m[tid] - M) : 0.f;
        if (tid == 0) {
            float L = 0.f;
#pragma unroll
            for (int i = 0; i < 8; i++)
                if (sm_l[i] > 0.f) L += sm_l[i] * __expf(sm_m[i] - M);
            g_m[idx] = M;
            g_l[idx] = L;
        }
    }
    __syncthreads();

    float a = 0.f;
#pragma unroll
    for (int i = 0; i < 8; i++)
        a += sm_w8[i] * sm_acc[i * DIM + tid];
    g_acc[(size_t)idx * DIM + tid] = a;
}

// ---------------------------------------------------------------------------
// Kernel 3: merge CHUNKS partials per batch row, normalize, write output.
// grid (BATCH, 4) x 64 threads: block handles dims [64*y, 64*y+64).
// Warp 0 computes merge weights; the dim loop is 32 unconditional, fully
// unrolled coalesced loads (max MLP). Masked chunks: weight=0, g_acc slot=0.
// ---------------------------------------------------------------------------
__global__ __launch_bounds__(64)
void reduce_kernel(float* __restrict__ out) {
    const int b   = blockIdx.x;
    const int d   = blockIdx.y * 64 + threadIdx.x;
    const int tid = threadIdx.x;

    __shared__ float wsh[CHUNKS];
    __shared__ float Lsh;

    if (tid < 32) {
        const float lc = g_l[b * CHUNKS + tid];
        const float mv = g_m[b * CHUNKS + tid];
        float M = (lc > 0.f) ? mv : -CUDART_INF_F;
#pragma unroll
        for (int off = 16; off; off >>= 1)
            M = fmaxf(M, __shfl_xor_sync(0xffffffffu, M, off));
        const float wgt = (lc > 0.f) ? __expf(mv - M) : 0.f;
        float L = lc * wgt;
#pragma unroll
        for (int off = 16; off; off >>= 1)
            L += __shfl_xor_sync(0xffffffffu, L, off);
        wsh[tid] = wgt;
        if (tid == 0) Lsh = L;
    }
    __syncthreads();

    const float* base = g_acc + (size_t)b * CHUNKS * DIM + d;
    float a = 0.f;
#pragma unroll
    for (int ci = 0; ci < CHUNKS; ci++)
        a += wsh[ci] * base[(size_t)ci * DIM];

    out[b * DIM + d] = a / Lsh;
}

// ---------------------------------------------------------------------------
// Launch. Inputs identified by element count (robust to metadata ordering):
//   query 16384 f32, attended 67108864 f32, sequence_lengths 64 (i32 or i64),
//   W 65536 f32, b 256 f32. Output: [B, D] f32.
// ---------------------------------------------------------------------------
extern "C" void kernel_launch(void* const* d_in, const int* in_sizes, int n_in,
                              void* d_out, int out_size) {
    const float* q = nullptr;
    const float* att = nullptr;
    const void*  lens = nullptr;
    const float* W = nullptr;
    const float* bias = nullptr;

    for (int i = 0; i < n_in; i++) {
        switch (in_sizes[i]) {
            case BATCH * DIM:                 q    = (const float*)d_in[i]; break;
            case S_TOTAL * BATCH * DIM:       att  = (const float*)d_in[i]; break;
            case BATCH:                       lens = d_in[i];               break;
            case DIM * DIM:                   W    = (const float*)d_in[i]; break;
            case DIM:                         bias = (const float*)d_in[i]; break;
            default: break;
        }
    }

    float* out = (float*)d_out;

    dim3 kgrid(BATCH, 8);
    key_kernel<<<kgrid, DIM>>>(q, W, bias, (const int*)lens);
    dim3 grid(CHUNKS, BATCH);
    flash_kernel<<<grid, DIM>>>(att, lens);
    dim3 rgrid(BATCH, 4);
    reduce_kernel<<<rgrid, 64>>>(out);
}